// round 12
// baseline (speedup 1.0000x reference)
#include <cuda_runtime.h>
#include <cuda_fp16.h>
#include <math.h>
#include <cstdint>

#define D_MODEL 1024
#define N_HEADS 16
#define D_KV    64
#define BATCH   2
#define SEQ     2048
#define M_TOTAL (BATCH*SEQ)     // 4096

// ---------------- scratch (device globals) ----------------------------------
__device__ half g_xh[(size_t)M_TOTAL*D_MODEL],  g_xl[(size_t)M_TOTAL*D_MODEL];
__device__ half g_wqh[(size_t)D_MODEL*D_MODEL];
__device__ half g_wkh[(size_t)D_MODEL*D_MODEL];
__device__ half g_wvh[(size_t)D_MODEL*D_MODEL];
__device__ half g_woh[(size_t)D_MODEL*D_MODEL];
__device__ half g_Qh[(size_t)M_TOTAL*D_MODEL],  g_Ql[(size_t)M_TOTAL*D_MODEL]; // [b,h,s,d]
__device__ half g_Kh[(size_t)M_TOTAL*D_MODEL];                                  // [b,h,s,d]
__device__ half g_Vh[(size_t)M_TOTAL*D_MODEL];
__device__ half g_Oh[(size_t)M_TOTAL*D_MODEL],  g_Ol[(size_t)M_TOTAL*D_MODEL]; // [b*s, h*64+d]
__device__ float g_cos[SEQ*(D_KV/2)];
__device__ float g_sin[SEQ*(D_KV/2)];

// ---------------- mma / ldmatrix / cp.async helpers --------------------------
__device__ __forceinline__ void ldsm4(uint32_t* r, uint32_t a) {
    asm volatile("ldmatrix.sync.aligned.m8n8.x4.shared.b16 {%0,%1,%2,%3}, [%4];"
        : "=r"(r[0]), "=r"(r[1]), "=r"(r[2]), "=r"(r[3]) : "r"(a));
}
__device__ __forceinline__ void ldsm4t(uint32_t* r, uint32_t a) {
    asm volatile("ldmatrix.sync.aligned.m8n8.x4.trans.shared.b16 {%0,%1,%2,%3}, [%4];"
        : "=r"(r[0]), "=r"(r[1]), "=r"(r[2]), "=r"(r[3]) : "r"(a));
}
__device__ __forceinline__ void mma16816(float* c, const uint32_t* a, const uint32_t* b) {
    asm volatile("mma.sync.aligned.m16n8k16.row.col.f32.f16.f16.f32 "
        "{%0,%1,%2,%3}, {%4,%5,%6,%7}, {%8,%9}, {%0,%1,%2,%3};"
        : "+f"(c[0]), "+f"(c[1]), "+f"(c[2]), "+f"(c[3])
        : "r"(a[0]), "r"(a[1]), "r"(a[2]), "r"(a[3]), "r"(b[0]), "r"(b[1]));
}
__device__ __forceinline__ void cpa16(uint32_t s, const void* g) {
    asm volatile("cp.async.cg.shared.global [%0], [%1], 16;" :: "r"(s), "l"(g));
}
#define CP_COMMIT() asm volatile("cp.async.commit_group;" ::: "memory")
#define CP_WAIT1()  asm volatile("cp.async.wait_group 1;" ::: "memory")
#define CP_WAIT0()  asm volatile("cp.async.wait_group 0;" ::: "memory")

// fp32 pair -> fp16 hi + fp16 lo words
__device__ __forceinline__ void packhl(float x, float y, uint32_t& h, uint32_t& l) {
    half2 hh = __floats2half2_rn(x, y);
    float2 hf = __half22float2(hh);
    half2 ll = __floats2half2_rn(x - hf.x, y - hf.y);
    h = *reinterpret_cast<uint32_t*>(&hh);
    l = *reinterpret_cast<uint32_t*>(&ll);
}
__device__ __forceinline__ uint32_t pack1(float x, float y) {
    half2 hh = __floats2half2_rn(x, y);
    return *reinterpret_cast<uint32_t*>(&hh);
}

// ---------------- fp32 -> fp16 hi/lo split (x) -------------------------------
__global__ void split_kernel(const float* __restrict__ src, half* __restrict__ hi,
                             half* __restrict__ lo, int n) {
    int i = (blockIdx.x * blockDim.x + threadIdx.x) * 4;
    if (i >= n) return;
    float4 v = *(const float4*)(src + i);
    uint32_t h0, l0, h1, l1;
    packhl(v.x, v.y, h0, l0);
    packhl(v.z, v.w, h1, l1);
    *(uint32_t*)(hi + i)     = h0; *(uint32_t*)(hi + i + 2) = h1;
    *(uint32_t*)(lo + i)     = l0; *(uint32_t*)(lo + i + 2) = l1;
}

// ---------------- fp32 -> fp16 convert (4 weights, one launch) ---------------
__global__ void cvtw_kernel(const float* __restrict__ w0, const float* __restrict__ w1,
                            const float* __restrict__ w2, const float* __restrict__ w3,
                            half* __restrict__ o0, half* __restrict__ o1,
                            half* __restrict__ o2, half* __restrict__ o3) {
    const int y = blockIdx.y;
    const float* s = (y == 0) ? w0 : (y == 1) ? w1 : (y == 2) ? w2 : w3;
    half* d = (y == 0) ? o0 : (y == 1) ? o1 : (y == 2) ? o2 : o3;
    int i = (blockIdx.x * blockDim.x + threadIdx.x) * 4;
    float4 v = *(const float4*)(s + i);
    *(uint32_t*)(d + i)     = pack1(v.x, v.y);
    *(uint32_t*)(d + i + 2) = pack1(v.z, v.w);
}

// ---------------- RoPE tables ------------------------------------------------
__global__ void rope_table_kernel() {
    int idx = blockIdx.x * blockDim.x + threadIdx.x;   // 2048*32
    int p   = idx & 31;
    int pos = idx >> 5;
    double freq = pow(10000.0, -(double)(2 * p) / 64.0);
    double ang  = (double)pos * freq;
    g_cos[idx] = (float)cos(ang);
    g_sin[idx] = (float)sin(ang);
}

// ---------------- HMMA fp16x2 GEMM, cp.async 3-stage, BK=64, 512 thr ---------
// C[m][n] = sum_k A[m][k]*B[n][k].  A = Ah+Al (fp16 split); B plain fp16.
// CTA tile: 128(M) x 256(N) x 64(K).  16 warps as 2(M) x 8(N); warp tile 64x32.
// 4 kk sub-iterations between barriers -> warps drift, tensor pipe stays fed.
#define G_RS     144                // smem row stride bytes (64 fp16 + 16B pad)
#define G_AH     0
#define G_AL     18432              // 128*144
#define G_B      36864
#define G_STAGE  73728              // + 256*144
#define G_NSTAGE 3

__global__ __launch_bounds__(512, 1)
void gemm_mma(const half* __restrict__ Ah, const half* __restrict__ Al,
              const half* __restrict__ B0, const half* __restrict__ B1,
              const half* __restrict__ B2,
              float* __restrict__ Cf, half* __restrict__ Qh, half* __restrict__ Ql,
              half* __restrict__ Kh, half* __restrict__ Vh,
              const int* __restrict__ tp, int qkv)
{
    extern __shared__ char sm[];
    const uint32_t smb = (uint32_t)__cvta_generic_to_shared(sm);
    const int tid = threadIdx.x, lane = tid & 31, wid = tid >> 5;
    const int wm = wid & 1, wn = wid >> 1;           // 2(M) x 8(N) warps
    const int m0 = blockIdx.y * 128, n0 = blockIdx.x * 256;
    const int z  = blockIdx.z;
    const half* W = qkv ? ((z == 0) ? B0 : (z == 1) ? B1 : B2) : B0;
    const int mode = qkv ? ((z == 0) ? 2 : (z == 1) ? 3 : 1) : 0;

    // loader mappings (512 thr, 8 cpa16 each per stage: 4 for A hi/lo, 4 for B)
    const int arow = tid >> 2, acol = (tid & 3) * 32;   // A: 4 thr/row, 32B each
    const int brow = tid >> 1, bcol = (tid & 1) * 64;   // B: 2 thr/row, 64B each
    const char* gAh = (const char*)(Ah + (size_t)(m0 + arow) * D_MODEL) + acol;
    const char* gAl = (const char*)(Al + (size_t)(m0 + arow) * D_MODEL) + acol;
    const char* gB  = (const char*)(W  + (size_t)(n0 + brow) * D_MODEL) + bcol;
    const uint32_t sA = smb + arow * G_RS + acol;
    const uint32_t sB = smb + G_B + brow * G_RS + bcol;

#define ISSUE(KT_, ST_) do { \
        const uint32_t so = (uint32_t)(ST_) * G_STAGE; \
        const int go = (KT_) * 128; \
        cpa16(so + sA,              gAh + go); \
        cpa16(so + sA + 16,         gAh + go + 16); \
        cpa16(so + sA + G_AL,       gAl + go); \
        cpa16(so + sA + G_AL + 16,  gAl + go + 16); \
        cpa16(so + sB,       gB + go); \
        cpa16(so + sB + 16,  gB + go + 16); \
        cpa16(so + sB + 32,  gB + go + 32); \
        cpa16(so + sB + 48,  gB + go + 48); \
        CP_COMMIT(); \
    } while (0)

    float acc[4][4][4];
#pragma unroll
    for (int i = 0; i < 4; i++)
#pragma unroll
        for (int j = 0; j < 4; j++)
#pragma unroll
            for (int k = 0; k < 4; k++) acc[i][j][k] = 0.f;

    ISSUE(0, 0);
    ISSUE(1, 1);

    const int KT = D_MODEL / 64;   // 16
    for (int kt = 0; kt < KT; kt++) {
        if (kt + 1 < KT) CP_WAIT1(); else CP_WAIT0();
        __syncthreads();
        // safe with 3 stages + <=1-iter warp skew
        if (kt + 2 < KT) ISSUE(kt + 2, (kt + 2) % G_NSTAGE);

        const uint32_t stb = smb + (kt % G_NSTAGE) * G_STAGE;
#pragma unroll
        for (int kk = 0; kk < 4; kk++) {
            uint32_t ah[4][4], al[4][4], bh[2][4];
#pragma unroll
            for (int mi = 0; mi < 4; mi++) {
                uint32_t a = stb + (wm * 64 + mi * 16 + (lane & 15)) * G_RS
                           + kk * 32 + (lane >> 4) * 16;
                ldsm4(ah[mi], a);
                ldsm4(al[mi], a + G_AL);
            }
#pragma unroll
            for (int L = 0; L < 2; L++) {
                uint32_t a = stb + G_B
                           + (wn * 32 + L * 16 + (lane & 7) + ((lane >> 4) & 1) * 8) * G_RS
                           + kk * 32 + ((lane >> 3) & 1) * 16;
                ldsm4(bh[L], a);
            }
            // hi sweep (16 independent MMAs), then lo sweep
#pragma unroll
            for (int mi = 0; mi < 4; mi++)
#pragma unroll
                for (int nf = 0; nf < 4; nf++)
                    mma16816(acc[mi][nf], ah[mi], &bh[nf >> 1][(nf & 1) * 2]);
#pragma unroll
            for (int mi = 0; mi < 4; mi++)
#pragma unroll
                for (int nf = 0; nf < 4; nf++)
                    mma16816(acc[mi][nf], al[mi], &bh[nf >> 1][(nf & 1) * 2]);
        }
    }

    // epilogue
#pragma unroll
    for (int mi = 0; mi < 4; mi++)
#pragma unroll
        for (int nf = 0; nf < 4; nf++) {
            const int row0 = m0 + wm * 64 + mi * 16 + (lane >> 2);
            const int col  = n0 + wn * 32 + nf * 8 + 2 * (lane & 3);
            float v0 = acc[mi][nf][0], v1 = acc[mi][nf][1];
            float v2 = acc[mi][nf][2], v3 = acc[mi][nf][3];
            if (mode >= 2) {  // RoPE
                const int p = (col & 63) >> 1;
                const int pos0 = tp[row0 & (SEQ - 1)];
                const int pos1 = tp[(row0 + 8) & (SEQ - 1)];
                const float c0 = g_cos[pos0 * 32 + p], s0 = g_sin[pos0 * 32 + p];
                const float c1 = g_cos[pos1 * 32 + p], s1 = g_sin[pos1 * 32 + p];
                float e0 = v0 * c0 - v1 * s0, o0 = v1 * c0 + v0 * s0;
                float e1 = v2 * c1 - v3 * s1, o1 = v3 * c1 + v2 * s1;
                v0 = e0; v1 = o0; v2 = e1; v3 = o1;
                if (mode == 2) { v0 *= 0.125f; v1 *= 0.125f; v2 *= 0.125f; v3 *= 0.125f; }
            }
            if (mode == 0) {
                *(float2*)(Cf + (size_t)row0 * D_MODEL + col)       = make_float2(v0, v1);
                *(float2*)(Cf + (size_t)(row0 + 8) * D_MODEL + col) = make_float2(v2, v3);
            } else {
                const int hh = col >> 6, d = col & 63;
                const int bb = row0 >> 11, ss = row0 & (SEQ - 1);
                size_t i0 = ((size_t)(bb * N_HEADS + hh) * SEQ + ss) * D_KV + d;
                size_t i1 = i0 + 8 * D_KV;
                if (mode == 2) {
                    uint32_t h0, l0, h1, l1;
                    packhl(v0, v1, h0, l0);
                    packhl(v2, v3, h1, l1);
                    *(uint32_t*)(Qh + i0) = h0; *(uint32_t*)(Ql + i0) = l0;
                    *(uint32_t*)(Qh + i1) = h1; *(uint32_t*)(Ql + i1) = l1;
                } else if (mode == 3) {
                    *(uint32_t*)(Kh + i0) = pack1(v0, v1);
                    *(uint32_t*)(Kh + i1) = pack1(v2, v3);
                } else {
                    *(uint32_t*)(Vh + i0) = pack1(v0, v1);
                    *(uint32_t*)(Vh + i1) = pack1(v2, v3);
                }
            }
        }
#undef ISSUE
}

// ---------------- tensor-core flash attention (causal, shifted-exp softmax) --
// block 256 thr = 8 warps, each warp 16 q-rows; key tiles of 64.
#define A_RS    144                 // 64 fp16 + pad
#define A_KT    (64*A_RS)           // 9216
#define A_STAGE (2*A_KT)            // 18432 (Kh, Vh)
#define QL_OFF  18432               // Q lo tile offset (128*144)
#define ST_OFF  36864               // KV stages start

__global__ __launch_bounds__(256, 1)
void attn_mma(const half* __restrict__ Qh_, const half* __restrict__ Ql_,
              const half* __restrict__ Kh_, const half* __restrict__ Vh_,
              half* __restrict__ Oh_, half* __restrict__ Ol_)
{
    extern __shared__ char sm[];
    const uint32_t smb = (uint32_t)__cvta_generic_to_shared(sm);
    const int tid = threadIdx.x, lane = tid & 31, wid = tid >> 5;
    const int qt = gridDim.x - 1 - blockIdx.x;      // heavy blocks first
    const int q0 = qt * 128;
    const int h = blockIdx.y, b = blockIdx.z;
    const size_t hb = (size_t)(b * N_HEADS + h) * SEQ * D_KV;
    const int nt = 2 * qt + 2;

    const half* Qh = Qh_ + hb; const half* Ql = Ql_ + hb;
    const half* Kh = Kh_ + hb; const half* Vh = Vh_ + hb;

    // load Q tile (hi+lo)
    {
        const int r = tid >> 1;
        const char* gqh = (const char*)(Qh + (size_t)(q0 + r) * D_KV);
        const char* gql = (const char*)(Ql + (size_t)(q0 + r) * D_KV);
        char* sq = sm + r * A_RS;
#pragma unroll
        for (int i = 0; i < 4; i++) {
            const int c = (tid & 1) * 64 + i * 16;
            *(uint4*)(sq + c)          = *(const uint4*)(gqh + c);
            *(uint4*)(sq + QL_OFF + c) = *(const uint4*)(gql + c);
        }
    }

    // KV loader mapping: 4 threads per row, 32B each (row = 128B)
    const int kr = tid >> 2;
    const int kc = (tid & 3) * 32;
    uint4 kbuf[2][2];
#define KV_LOAD(KT_) do { \
        const size_t roff = (size_t)((KT_) * 64 + kr) * D_KV; \
        const char* t0 = (const char*)(Kh + roff); \
        const char* t1 = (const char*)(Vh + roff); \
        kbuf[0][0] = *(const uint4*)(t0 + kc); kbuf[0][1] = *(const uint4*)(t0 + kc + 16); \
        kbuf[1][0] = *(const uint4*)(t1 + kc); kbuf[1][1] = *(const uint4*)(t1 + kc + 16); \
    } while (0)
#define KV_STORE(ST_) do { \
        char* dst = sm + ST_OFF + (ST_) * A_STAGE + kr * A_RS + kc; \
        *(uint4*)(dst)             = kbuf[0][0]; \
        *(uint4*)(dst + 16)        = kbuf[0][1]; \
        *(uint4*)(dst + A_KT)      = kbuf[1][0]; \
        *(uint4*)(dst + A_KT + 16) = kbuf[1][1]; \
    } while (0)

    KV_LOAD(0);
    KV_STORE(0);
    __syncthreads();

    // Q fragments
    uint32_t qh[4][4], ql[4][4];
#pragma unroll
    for (int kk = 0; kk < 4; kk++) {
        uint32_t a = smb + (wid * 16 + (lane & 15)) * A_RS + kk * 32 + (lane >> 4) * 16;
        ldsm4(qh[kk], a);
        ldsm4(ql[kk], a + QL_OFF);
    }

    float oacc[8][4];
#pragma unroll
    for (int i = 0; i < 8; i++)
#pragma unroll
        for (int j = 0; j < 4; j++) oacc[i][j] = 0.f;
    float ls0 = 0.f, ls1 = 0.f;
    const int wr0 = q0 + wid * 16;

    for (int kt = 0; kt < nt; kt++) {
        if (kt + 1 < nt) KV_LOAD(kt + 1);
        const uint32_t stb = smb + ST_OFF + (kt & 1) * A_STAGE;
        const int kbase = kt * 64;

        if (kbase <= wr0 + 15) {
            float sacc[8][4];
#pragma unroll
            for (int i = 0; i < 8; i++)
#pragma unroll
                for (int j = 0; j < 4; j++) sacc[i][j] = 0.f;

            // S = (Qh+Ql) Kh^T  -- hi sweep then lo sweep per kk
#pragma unroll
            for (int kk = 0; kk < 4; kk++) {
                uint32_t kbh[4][4];
#pragma unroll
                for (int L = 0; L < 4; L++) {
                    uint32_t a = stb + (L * 16 + (lane & 7) + ((lane >> 4) & 1) * 8) * A_RS
                               + kk * 32 + ((lane >> 3) & 1) * 16;
                    ldsm4(kbh[L], a);
                }
#pragma unroll
                for (int nf = 0; nf < 8; nf++)
                    mma16816(sacc[nf], qh[kk], &kbh[nf >> 1][(nf & 1) * 2]);
#pragma unroll
                for (int nf = 0; nf < 8; nf++)
                    mma16816(sacc[nf], ql[kk], &kbh[nf >> 1][(nf & 1) * 2]);
            }

            // mask + shifted exp (p = e^(s-6); shift cancels in normalization)
            const bool needm = (kbase + 63 > wr0);
#pragma unroll
            for (int nf = 0; nf < 8; nf++)
#pragma unroll
                for (int j = 0; j < 4; j++) {
                    float p = __expf(sacc[nf][j] - 6.0f);
                    if (needm) {
                        const int key = kbase + nf * 8 + 2 * (lane & 3) + (j & 1);
                        const int row = wr0 + (lane >> 2) + (j >> 1) * 8;
                        if (key > row) p = 0.f;
                    }
                    sacc[nf][j] = p;
                    if (j < 2) ls0 += p; else ls1 += p;
                }

            // O += (Ph+Pl) Vh  -- hi sweep then lo sweep per kk2
#pragma unroll
            for (int kk2 = 0; kk2 < 4; kk2++) {
                uint32_t vh[4][4];
#pragma unroll
                for (int dL = 0; dL < 4; dL++) {
                    uint32_t a = stb + A_KT
                               + (kk2 * 16 + (lane & 7) + ((lane >> 3) & 1) * 8) * A_RS
                               + dL * 32 + ((lane >> 4) & 1) * 16;
                    ldsm4t(vh[dL], a);
                }
                uint32_t ph[4], pl[4];
                packhl(sacc[2*kk2][0],   sacc[2*kk2][1],   ph[0], pl[0]);
                packhl(sacc[2*kk2][2],   sacc[2*kk2][3],   ph[1], pl[1]);
                packhl(sacc[2*kk2+1][0], sacc[2*kk2+1][1], ph[2], pl[2]);
                packhl(sacc[2*kk2+1][2], sacc[2*kk2+1][3], ph[3], pl[3]);
#pragma unroll
                for (int df = 0; df < 8; df++)
                    mma16816(oacc[df], ph, &vh[df >> 1][(df & 1) * 2]);
#pragma unroll
                for (int df = 0; df < 8; df++)
                    mma16816(oacc[df], pl, &vh[df >> 1][(df & 1) * 2]);
            }
        }

        if (kt + 1 < nt) KV_STORE((kt + 1) & 1);
        __syncthreads();
    }

    // reduce row sums across quad
    ls0 += __shfl_xor_sync(0xffffffffu, ls0, 1);
    ls0 += __shfl_xor_sync(0xffffffffu, ls0, 2);
    ls1 += __shfl_xor_sync(0xffffffffu, ls1, 1);
    ls1 += __shfl_xor_sync(0xffffffffu, ls1, 2);
    const float inv0 = 1.f / ls0, inv1 = 1.f / ls1;

    const int row0 = q0 + wid * 16 + (lane >> 2);
#pragma unroll
    for (int df = 0; df < 8; df++) {
        const int d = df * 8 + 2 * (lane & 3);
        const float v0 = oacc[df][0] * inv0, v1 = oacc[df][1] * inv0;
        const float v2 = oacc[df][2] * inv1, v3 = oacc[df][3] * inv1;
        const size_t i0 = (size_t)(b * SEQ + row0) * D_MODEL + h * D_KV + d;
        const size_t i1 = i0 + (size_t)8 * D_MODEL;
        uint32_t h0, l0, h1, l1;
        packhl(v0, v1, h0, l0);
        packhl(v2, v3, h1, l1);
        *(uint32_t*)(Oh_ + i0) = h0; *(uint32_t*)(Ol_ + i0) = l0;
        *(uint32_t*)(Oh_ + i1) = h1; *(uint32_t*)(Ol_ + i1) = l1;
    }
}

// ---------------- host launcher ----------------------------------------------
extern "C" void kernel_launch(void* const* d_in, const int* in_sizes, int n_in,
                              void* d_out, int out_size)
{
    const float* x  = (const float*)d_in[0];
    const float* wq = (const float*)d_in[1];
    const float* wk = (const float*)d_in[2];
    const float* wv = (const float*)d_in[3];
    const float* wo = (const float*)d_in[4];
    const int*   tp = (const int*)d_in[5];
    float* out = (float*)d_out;

    half *xh, *xl, *wqh, *wkh, *wvh, *woh;
    half *Qh, *Ql, *Kh, *Vh, *Oh, *Ol;
    cudaGetSymbolAddress((void**)&xh, g_xh);   cudaGetSymbolAddress((void**)&xl, g_xl);
    cudaGetSymbolAddress((void**)&wqh, g_wqh); cudaGetSymbolAddress((void**)&wkh, g_wkh);
    cudaGetSymbolAddress((void**)&wvh, g_wvh); cudaGetSymbolAddress((void**)&woh, g_woh);
    cudaGetSymbolAddress((void**)&Qh, g_Qh);   cudaGetSymbolAddress((void**)&Ql, g_Ql);
    cudaGetSymbolAddress((void**)&Kh, g_Kh);   cudaGetSymbolAddress((void**)&Vh, g_Vh);
    cudaGetSymbolAddress((void**)&Oh, g_Oh);   cudaGetSymbolAddress((void**)&Ol, g_Ol);

    const int gemm_smem = G_NSTAGE * G_STAGE;                 // 221184
    const int attn_smem = ST_OFF + 2 * A_STAGE;               // 73728
    cudaFuncSetAttribute(gemm_mma, cudaFuncAttributeMaxDynamicSharedMemorySize, gemm_smem);
    cudaFuncSetAttribute(attn_mma, cudaFuncAttributeMaxDynamicSharedMemorySize, attn_smem);

    // splits / converts / tables (3 launches)
    split_kernel<<<M_TOTAL * D_MODEL / 1024, 256>>>(x, xh, xl, M_TOTAL * D_MODEL);
    cvtw_kernel<<<dim3(D_MODEL * D_MODEL / 1024, 4), 256>>>(wq, wk, wv, wo,
                                                            wqh, wkh, wvh, woh);
    rope_table_kernel<<<SEQ * 32 / 256, 256>>>();

    // fused QKV projections (one launch, 512 threads)
    dim3 qkvgrid(D_MODEL / 256, M_TOTAL / 128, 3);   // (4, 32, 3)
    gemm_mma<<<qkvgrid, 512, gemm_smem>>>(xh, xl, wqh, wkh, wvh,
                                          nullptr, Qh, Ql, Kh, Vh, tp, 1);

    // attention
    dim3 agrid(SEQ / 128, N_HEADS, BATCH);           // (16,16,2)
    attn_mma<<<agrid, 256, attn_smem>>>(Qh, Ql, Kh, Vh, Oh, Ol);

    // output projection
    dim3 ogrid(D_MODEL / 256, M_TOTAL / 128, 1);
    gemm_mma<<<ogrid, 512, gemm_smem>>>(Oh, Ol, woh, nullptr, nullptr,
                                        out, nullptr, nullptr, nullptr, nullptr, tp, 0);
}

// round 13
// speedup vs baseline: 1.4286x; 1.4286x over previous
#include <cuda_runtime.h>
#include <cuda_fp16.h>
#include <math.h>
#include <cstdint>

#define D_MODEL 1024
#define N_HEADS 16
#define D_KV    64
#define BATCH   2
#define SEQ     2048
#define M_TOTAL (BATCH*SEQ)     // 4096

// ---------------- scratch (device globals) ----------------------------------
__device__ half g_xh[(size_t)M_TOTAL*D_MODEL];
__device__ half g_wqh[(size_t)D_MODEL*D_MODEL];
__device__ half g_wkh[(size_t)D_MODEL*D_MODEL];
__device__ half g_wvh[(size_t)D_MODEL*D_MODEL];
__device__ half g_woh[(size_t)D_MODEL*D_MODEL];
__device__ half g_Qh[(size_t)M_TOTAL*D_MODEL];   // [b,h,s,d]
__device__ half g_Kh[(size_t)M_TOTAL*D_MODEL];   // [b,h,s,d]
__device__ half g_Vh[(size_t)M_TOTAL*D_MODEL];
__device__ half g_Oh[(size_t)M_TOTAL*D_MODEL];   // [b*s, h*64+d]
__device__ float g_cos[SEQ*(D_KV/2)];
__device__ float g_sin[SEQ*(D_KV/2)];

// ---------------- mma / ldmatrix / cp.async helpers --------------------------
__device__ __forceinline__ void ldsm4(uint32_t* r, uint32_t a) {
    asm volatile("ldmatrix.sync.aligned.m8n8.x4.shared.b16 {%0,%1,%2,%3}, [%4];"
        : "=r"(r[0]), "=r"(r[1]), "=r"(r[2]), "=r"(r[3]) : "r"(a));
}
__device__ __forceinline__ void ldsm4t(uint32_t* r, uint32_t a) {
    asm volatile("ldmatrix.sync.aligned.m8n8.x4.trans.shared.b16 {%0,%1,%2,%3}, [%4];"
        : "=r"(r[0]), "=r"(r[1]), "=r"(r[2]), "=r"(r[3]) : "r"(a));
}
__device__ __forceinline__ void mma16816(float* c, const uint32_t* a, const uint32_t* b) {
    asm volatile("mma.sync.aligned.m16n8k16.row.col.f32.f16.f16.f32 "
        "{%0,%1,%2,%3}, {%4,%5,%6,%7}, {%8,%9}, {%0,%1,%2,%3};"
        : "+f"(c[0]), "+f"(c[1]), "+f"(c[2]), "+f"(c[3])
        : "r"(a[0]), "r"(a[1]), "r"(a[2]), "r"(a[3]), "r"(b[0]), "r"(b[1]));
}
__device__ __forceinline__ void cpa16(uint32_t s, const void* g) {
    asm volatile("cp.async.cg.shared.global [%0], [%1], 16;" :: "r"(s), "l"(g));
}
#define CP_COMMIT() asm volatile("cp.async.commit_group;" ::: "memory")
#define CP_WAIT1()  asm volatile("cp.async.wait_group 1;" ::: "memory")
#define CP_WAIT0()  asm volatile("cp.async.wait_group 0;" ::: "memory")

__device__ __forceinline__ uint32_t pack1(float x, float y) {
    half2 hh = __floats2half2_rn(x, y);
    return *reinterpret_cast<uint32_t*>(&hh);
}

// ---------------- fp32 -> fp16 convert (x) -----------------------------------
__global__ void cvtx_kernel(const float* __restrict__ src, half* __restrict__ dst) {
    int i = (blockIdx.x * blockDim.x + threadIdx.x) * 4;
    float4 v = *(const float4*)(src + i);
    *(uint32_t*)(dst + i)     = pack1(v.x, v.y);
    *(uint32_t*)(dst + i + 2) = pack1(v.z, v.w);
}

// ---------------- fp32 -> fp16 convert (4 weights, one launch) ---------------
__global__ void cvtw_kernel(const float* __restrict__ w0, const float* __restrict__ w1,
                            const float* __restrict__ w2, const float* __restrict__ w3,
                            half* __restrict__ o0, half* __restrict__ o1,
                            half* __restrict__ o2, half* __restrict__ o3) {
    const int y = blockIdx.y;
    const float* s = (y == 0) ? w0 : (y == 1) ? w1 : (y == 2) ? w2 : w3;
    half* d = (y == 0) ? o0 : (y == 1) ? o1 : (y == 2) ? o2 : o3;
    int i = (blockIdx.x * blockDim.x + threadIdx.x) * 4;
    float4 v = *(const float4*)(s + i);
    *(uint32_t*)(d + i)     = pack1(v.x, v.y);
    *(uint32_t*)(d + i + 2) = pack1(v.z, v.w);
}

// ---------------- RoPE tables ------------------------------------------------
__global__ void rope_table_kernel() {
    int idx = blockIdx.x * blockDim.x + threadIdx.x;   // 2048*32
    int p   = idx & 31;
    int pos = idx >> 5;
    double freq = pow(10000.0, -(double)(2 * p) / 64.0);
    double ang  = (double)pos * freq;
    g_cos[idx] = (float)cos(ang);
    g_sin[idx] = (float)sin(ang);
}

// ---------------- HMMA fp16 GEMM, cp.async 3-stage, BK=32, 512 thr -----------
// C[m][n] = sum_k A[m][k]*B[n][k], both operands fp16.
// CTA tile: 128(M) x 256(N) x 32(K).  16 warps as 2(M) x 8(N); warp tile 64x32.
// qkv=1: grid.z selects {0:Q(RoPE,x0.125) 1:K(RoPE) 2:V}; qkv=0: fp32 out.
#define G_RS     80                 // smem row stride bytes (32 fp16 + pad)
#define G_A      0
#define G_B      10240              // 128*80
#define G_STAGE  30720              // + 256*80
#define G_NSTAGE 3

__global__ __launch_bounds__(512, 1)
void gemm_mma(const half* __restrict__ A,
              const half* __restrict__ B0, const half* __restrict__ B1,
              const half* __restrict__ B2,
              float* __restrict__ Cf, half* __restrict__ Qd,
              half* __restrict__ Kd, half* __restrict__ Vd,
              const int* __restrict__ tp, int qkv)
{
    extern __shared__ char sm[];
    const uint32_t smb = (uint32_t)__cvta_generic_to_shared(sm);
    const int tid = threadIdx.x, lane = tid & 31, wid = tid >> 5;
    const int wm = wid & 1, wn = wid >> 1;           // 2(M) x 8(N) warps
    const int m0 = blockIdx.y * 128, n0 = blockIdx.x * 256;
    const int z  = blockIdx.z;
    const half* W = qkv ? ((z == 0) ? B0 : (z == 1) ? B1 : B2) : B0;
    const int mode = qkv ? ((z == 0) ? 2 : (z == 1) ? 3 : 1) : 0;

    // loader mappings (512 thr, 3 cpa16 each per stage)
    const int arow = tid >> 2, acol = (tid & 3) * 16;   // A: 4 thr/row, 16B each
    const int brow = tid >> 1, bcol = (tid & 1) * 32;   // B: 2 thr/row, 32B each
    const char* gA = (const char*)(A + (size_t)(m0 + arow) * D_MODEL) + acol;
    const char* gB = (const char*)(W + (size_t)(n0 + brow) * D_MODEL) + bcol;
    const uint32_t sA = smb + arow * G_RS + acol;
    const uint32_t sB = smb + G_B + brow * G_RS + bcol;

#define ISSUE(KT_, ST_) do { \
        const uint32_t so = (uint32_t)(ST_) * G_STAGE; \
        const int go = (KT_) * 64; \
        cpa16(so + sA,       gA + go); \
        cpa16(so + sB,       gB + go); \
        cpa16(so + sB + 16,  gB + go + 16); \
        CP_COMMIT(); \
    } while (0)

    float acc[4][4][4];
#pragma unroll
    for (int i = 0; i < 4; i++)
#pragma unroll
        for (int j = 0; j < 4; j++)
#pragma unroll
            for (int k = 0; k < 4; k++) acc[i][j][k] = 0.f;

    ISSUE(0, 0);
    ISSUE(1, 1);

    const int KT = D_MODEL / 32;   // 32
    for (int kt = 0; kt < KT; kt++) {
        if (kt + 1 < KT) CP_WAIT1(); else CP_WAIT0();
        __syncthreads();
        if (kt + 2 < KT) ISSUE(kt + 2, (kt + 2) % G_NSTAGE);

        const uint32_t stb = smb + (kt % G_NSTAGE) * G_STAGE;
#pragma unroll
        for (int kk = 0; kk < 2; kk++) {
            uint32_t ah[4][4], bh[2][4];
#pragma unroll
            for (int mi = 0; mi < 4; mi++) {
                uint32_t a = stb + (wm * 64 + mi * 16 + (lane & 15)) * G_RS
                           + kk * 32 + (lane >> 4) * 16;
                ldsm4(ah[mi], a);
            }
#pragma unroll
            for (int L = 0; L < 2; L++) {
                uint32_t a = stb + G_B
                           + (wn * 32 + L * 16 + (lane & 7) + ((lane >> 4) & 1) * 8) * G_RS
                           + kk * 32 + ((lane >> 3) & 1) * 16;
                ldsm4(bh[L], a);
            }
#pragma unroll
            for (int mi = 0; mi < 4; mi++)
#pragma unroll
                for (int nf = 0; nf < 4; nf++)
                    mma16816(acc[mi][nf], ah[mi], &bh[nf >> 1][(nf & 1) * 2]);
        }
    }

    // epilogue
#pragma unroll
    for (int mi = 0; mi < 4; mi++)
#pragma unroll
        for (int nf = 0; nf < 4; nf++) {
            const int row0 = m0 + wm * 64 + mi * 16 + (lane >> 2);
            const int col  = n0 + wn * 32 + nf * 8 + 2 * (lane & 3);
            float v0 = acc[mi][nf][0], v1 = acc[mi][nf][1];
            float v2 = acc[mi][nf][2], v3 = acc[mi][nf][3];
            if (mode >= 2) {  // RoPE
                const int p = (col & 63) >> 1;
                const int pos0 = tp[row0 & (SEQ - 1)];
                const int pos1 = tp[(row0 + 8) & (SEQ - 1)];
                const float c0 = g_cos[pos0 * 32 + p], s0 = g_sin[pos0 * 32 + p];
                const float c1 = g_cos[pos1 * 32 + p], s1 = g_sin[pos1 * 32 + p];
                float e0 = v0 * c0 - v1 * s0, o0 = v1 * c0 + v0 * s0;
                float e1 = v2 * c1 - v3 * s1, o1 = v3 * c1 + v2 * s1;
                v0 = e0; v1 = o0; v2 = e1; v3 = o1;
                if (mode == 2) { v0 *= 0.125f; v1 *= 0.125f; v2 *= 0.125f; v3 *= 0.125f; }
            }
            if (mode == 0) {
                *(float2*)(Cf + (size_t)row0 * D_MODEL + col)       = make_float2(v0, v1);
                *(float2*)(Cf + (size_t)(row0 + 8) * D_MODEL + col) = make_float2(v2, v3);
            } else {
                const int hh = col >> 6, d = col & 63;
                const int bb = row0 >> 11, ss = row0 & (SEQ - 1);
                size_t i0 = ((size_t)(bb * N_HEADS + hh) * SEQ + ss) * D_KV + d;
                size_t i1 = i0 + 8 * D_KV;
                half* dst = (mode == 2) ? Qd : (mode == 3) ? Kd : Vd;
                *(uint32_t*)(dst + i0) = pack1(v0, v1);
                *(uint32_t*)(dst + i1) = pack1(v2, v3);
            }
        }
#undef ISSUE
}

// ---------------- tensor-core flash attention (causal, shifted-exp softmax) --
// block 256 thr = 8 warps, each warp 16 q-rows; key tiles of 64.  Pure fp16 ops.
#define A_RS    144                 // 64 fp16 + pad
#define A_KT    (64*A_RS)           // 9216
#define A_STAGE (2*A_KT)            // 18432 (Kh, Vh)
#define ST_OFF  18432               // KV stages start (after 128-row Q tile)

__global__ __launch_bounds__(256, 1)
void attn_mma(const half* __restrict__ Qh_, const half* __restrict__ Kh_,
              const half* __restrict__ Vh_, half* __restrict__ Oh_)
{
    extern __shared__ char sm[];
    const uint32_t smb = (uint32_t)__cvta_generic_to_shared(sm);
    const int tid = threadIdx.x, lane = tid & 31, wid = tid >> 5;
    const int qt = gridDim.x - 1 - blockIdx.x;      // heavy blocks first
    const int q0 = qt * 128;
    const int h = blockIdx.y, b = blockIdx.z;
    const size_t hb = (size_t)(b * N_HEADS + h) * SEQ * D_KV;
    const int nt = 2 * qt + 2;

    const half* Qh = Qh_ + hb;
    const half* Kh = Kh_ + hb;
    const half* Vh = Vh_ + hb;

    // load Q tile
    {
        const int r = tid >> 1;
        const char* gqh = (const char*)(Qh + (size_t)(q0 + r) * D_KV);
        char* sq = sm + r * A_RS;
#pragma unroll
        for (int i = 0; i < 4; i++) {
            const int c = (tid & 1) * 64 + i * 16;
            *(uint4*)(sq + c) = *(const uint4*)(gqh + c);
        }
    }

    // KV loader mapping: 4 threads per row, 32B each (row = 128B)
    const int kr = tid >> 2;
    const int kc = (tid & 3) * 32;
    uint4 kbuf[2][2];
#define KV_LOAD(KT_) do { \
        const size_t roff = (size_t)((KT_) * 64 + kr) * D_KV; \
        const char* t0 = (const char*)(Kh + roff); \
        const char* t1 = (const char*)(Vh + roff); \
        kbuf[0][0] = *(const uint4*)(t0 + kc); kbuf[0][1] = *(const uint4*)(t0 + kc + 16); \
        kbuf[1][0] = *(const uint4*)(t1 + kc); kbuf[1][1] = *(const uint4*)(t1 + kc + 16); \
    } while (0)
#define KV_STORE(ST_) do { \
        char* dst = sm + ST_OFF + (ST_) * A_STAGE + kr * A_RS + kc; \
        *(uint4*)(dst)             = kbuf[0][0]; \
        *(uint4*)(dst + 16)        = kbuf[0][1]; \
        *(uint4*)(dst + A_KT)      = kbuf[1][0]; \
        *(uint4*)(dst + A_KT + 16) = kbuf[1][1]; \
    } while (0)

    KV_LOAD(0);
    KV_STORE(0);
    __syncthreads();

    // Q fragments
    uint32_t qh[4][4];
#pragma unroll
    for (int kk = 0; kk < 4; kk++) {
        uint32_t a = smb + (wid * 16 + (lane & 15)) * A_RS + kk * 32 + (lane >> 4) * 16;
        ldsm4(qh[kk], a);
    }

    float oacc[8][4];
#pragma unroll
    for (int i = 0; i < 8; i++)
#pragma unroll
        for (int j = 0; j < 4; j++) oacc[i][j] = 0.f;
    float ls0 = 0.f, ls1 = 0.f;
    const int wr0 = q0 + wid * 16;

    for (int kt = 0; kt < nt; kt++) {
        if (kt + 1 < nt) KV_LOAD(kt + 1);
        const uint32_t stb = smb + ST_OFF + (kt & 1) * A_STAGE;
        const int kbase = kt * 64;

        if (kbase <= wr0 + 15) {
            float sacc[8][4];
#pragma unroll
            for (int i = 0; i < 8; i++)
#pragma unroll
                for (int j = 0; j < 4; j++) sacc[i][j] = 0.f;

            // S = Q K^T
#pragma unroll
            for (int kk = 0; kk < 4; kk++) {
                uint32_t kbh[4][4];
#pragma unroll
                for (int L = 0; L < 4; L++) {
                    uint32_t a = stb + (L * 16 + (lane & 7) + ((lane >> 4) & 1) * 8) * A_RS
                               + kk * 32 + ((lane >> 3) & 1) * 16;
                    ldsm4(kbh[L], a);
                }
#pragma unroll
                for (int nf = 0; nf < 8; nf++)
                    mma16816(sacc[nf], qh[kk], &kbh[nf >> 1][(nf & 1) * 2]);
            }

            // mask + shifted exp (p = e^(s-6); shift cancels in normalization)
            const bool needm = (kbase + 63 > wr0);
#pragma unroll
            for (int nf = 0; nf < 8; nf++)
#pragma unroll
                for (int j = 0; j < 4; j++) {
                    float p = __expf(sacc[nf][j] - 6.0f);
                    if (needm) {
                        const int key = kbase + nf * 8 + 2 * (lane & 3) + (j & 1);
                        const int row = wr0 + (lane >> 2) + (j >> 1) * 8;
                        if (key > row) p = 0.f;
                    }
                    sacc[nf][j] = p;
                    if (j < 2) ls0 += p; else ls1 += p;
                }

            // O += P V
#pragma unroll
            for (int kk2 = 0; kk2 < 4; kk2++) {
                uint32_t vh[4][4];
#pragma unroll
                for (int dL = 0; dL < 4; dL++) {
                    uint32_t a = stb + A_KT
                               + (kk2 * 16 + (lane & 7) + ((lane >> 3) & 1) * 8) * A_RS
                               + dL * 32 + ((lane >> 4) & 1) * 16;
                    ldsm4t(vh[dL], a);
                }
                uint32_t ph[4];
                ph[0] = pack1(sacc[2*kk2][0],   sacc[2*kk2][1]);
                ph[1] = pack1(sacc[2*kk2][2],   sacc[2*kk2][3]);
                ph[2] = pack1(sacc[2*kk2+1][0], sacc[2*kk2+1][1]);
                ph[3] = pack1(sacc[2*kk2+1][2], sacc[2*kk2+1][3]);
#pragma unroll
                for (int df = 0; df < 8; df++)
                    mma16816(oacc[df], ph, &vh[df >> 1][(df & 1) * 2]);
            }
        }

        if (kt + 1 < nt) KV_STORE((kt + 1) & 1);
        __syncthreads();
    }

    // reduce row sums across quad
    ls0 += __shfl_xor_sync(0xffffffffu, ls0, 1);
    ls0 += __shfl_xor_sync(0xffffffffu, ls0, 2);
    ls1 += __shfl_xor_sync(0xffffffffu, ls1, 1);
    ls1 += __shfl_xor_sync(0xffffffffu, ls1, 2);
    const float inv0 = 1.f / ls0, inv1 = 1.f / ls1;

    const int row0 = q0 + wid * 16 + (lane >> 2);
#pragma unroll
    for (int df = 0; df < 8; df++) {
        const int d = df * 8 + 2 * (lane & 3);
        const float v0 = oacc[df][0] * inv0, v1 = oacc[df][1] * inv0;
        const float v2 = oacc[df][2] * inv1, v3 = oacc[df][3] * inv1;
        const size_t i0 = (size_t)(b * SEQ + row0) * D_MODEL + h * D_KV + d;
        const size_t i1 = i0 + (size_t)8 * D_MODEL;
        *(uint32_t*)(Oh_ + i0) = pack1(v0, v1);
        *(uint32_t*)(Oh_ + i1) = pack1(v2, v3);
    }
}

// ---------------- host launcher ----------------------------------------------
extern "C" void kernel_launch(void* const* d_in, const int* in_sizes, int n_in,
                              void* d_out, int out_size)
{
    const float* x  = (const float*)d_in[0];
    const float* wq = (const float*)d_in[1];
    const float* wk = (const float*)d_in[2];
    const float* wv = (const float*)d_in[3];
    const float* wo = (const float*)d_in[4];
    const int*   tp = (const int*)d_in[5];
    float* out = (float*)d_out;

    half *xh, *wqh, *wkh, *wvh, *woh, *Qh, *Kh, *Vh, *Oh;
    cudaGetSymbolAddress((void**)&xh, g_xh);
    cudaGetSymbolAddress((void**)&wqh, g_wqh); cudaGetSymbolAddress((void**)&wkh, g_wkh);
    cudaGetSymbolAddress((void**)&wvh, g_wvh); cudaGetSymbolAddress((void**)&woh, g_woh);
    cudaGetSymbolAddress((void**)&Qh, g_Qh);   cudaGetSymbolAddress((void**)&Kh, g_Kh);
    cudaGetSymbolAddress((void**)&Vh, g_Vh);   cudaGetSymbolAddress((void**)&Oh, g_Oh);

    const int gemm_smem = G_NSTAGE * G_STAGE;                 // 92160
    const int attn_smem = ST_OFF + 2 * A_STAGE;               // 55296
    cudaFuncSetAttribute(gemm_mma, cudaFuncAttributeMaxDynamicSharedMemorySize, gemm_smem);
    cudaFuncSetAttribute(attn_mma, cudaFuncAttributeMaxDynamicSharedMemorySize, attn_smem);

    // converts / tables (3 launches)
    cvtx_kernel<<<M_TOTAL * D_MODEL / 1024, 256>>>(x, xh);
    cvtw_kernel<<<dim3(D_MODEL * D_MODEL / 1024, 4), 256>>>(wq, wk, wv, wo,
                                                            wqh, wkh, wvh, woh);
    rope_table_kernel<<<SEQ * 32 / 256, 256>>>();

    // fused QKV projections (one launch, 512 threads)
    dim3 qkvgrid(D_MODEL / 256, M_TOTAL / 128, 3);   // (4, 32, 3)
    gemm_mma<<<qkvgrid, 512, gemm_smem>>>(xh, wqh, wkh, wvh,
                                          nullptr, Qh, Kh, Vh, tp, 1);

    // attention
    dim3 agrid(SEQ / 128, N_HEADS, BATCH);           // (16,16,2)
    attn_mma<<<agrid, 256, attn_smem>>>(Qh, Kh, Vh, Oh);

    // output projection
    dim3 ogrid(D_MODEL / 256, M_TOTAL / 128, 1);
    gemm_mma<<<ogrid, 512, gemm_smem>>>(Oh, woh, nullptr, nullptr,
                                        out, nullptr, nullptr, nullptr, tp, 0);
}

// round 14
// speedup vs baseline: 1.4414x; 1.0089x over previous
#include <cuda_runtime.h>
#include <cuda_fp16.h>
#include <math.h>
#include <cstdint>

#define D_MODEL 1024
#define N_HEADS 16
#define D_KV    64
#define BATCH   2
#define SEQ     2048
#define M_TOTAL (BATCH*SEQ)     // 4096

// ---------------- scratch (device globals) ----------------------------------
__device__ half g_xh[(size_t)M_TOTAL*D_MODEL];
__device__ half g_wqh[(size_t)D_MODEL*D_MODEL];
__device__ half g_wkh[(size_t)D_MODEL*D_MODEL];
__device__ half g_wvh[(size_t)D_MODEL*D_MODEL];
__device__ half g_woh[(size_t)D_MODEL*D_MODEL];
__device__ half g_Qh[(size_t)M_TOTAL*D_MODEL];   // [b,h,s,d]
__device__ half g_Kh[(size_t)M_TOTAL*D_MODEL];   // [b,h,s,d]
__device__ half g_Vh[(size_t)M_TOTAL*D_MODEL];
__device__ half g_Oh[(size_t)M_TOTAL*D_MODEL];   // [b*s, h*64+d]
__device__ float g_cos[SEQ*(D_KV/2)];
__device__ float g_sin[SEQ*(D_KV/2)];

// ---------------- mma / ldmatrix / cp.async helpers --------------------------
__device__ __forceinline__ void ldsm4(uint32_t* r, uint32_t a) {
    asm volatile("ldmatrix.sync.aligned.m8n8.x4.shared.b16 {%0,%1,%2,%3}, [%4];"
        : "=r"(r[0]), "=r"(r[1]), "=r"(r[2]), "=r"(r[3]) : "r"(a));
}
__device__ __forceinline__ void ldsm4t(uint32_t* r, uint32_t a) {
    asm volatile("ldmatrix.sync.aligned.m8n8.x4.trans.shared.b16 {%0,%1,%2,%3}, [%4];"
        : "=r"(r[0]), "=r"(r[1]), "=r"(r[2]), "=r"(r[3]) : "r"(a));
}
__device__ __forceinline__ void mma16816(float* c, const uint32_t* a, const uint32_t* b) {
    asm volatile("mma.sync.aligned.m16n8k16.row.col.f32.f16.f16.f32 "
        "{%0,%1,%2,%3}, {%4,%5,%6,%7}, {%8,%9}, {%0,%1,%2,%3};"
        : "+f"(c[0]), "+f"(c[1]), "+f"(c[2]), "+f"(c[3])
        : "r"(a[0]), "r"(a[1]), "r"(a[2]), "r"(a[3]), "r"(b[0]), "r"(b[1]));
}
__device__ __forceinline__ void cpa16(uint32_t s, const void* g) {
    asm volatile("cp.async.cg.shared.global [%0], [%1], 16;" :: "r"(s), "l"(g));
}
#define CP_COMMIT() asm volatile("cp.async.commit_group;" ::: "memory")
#define CP_WAIT1()  asm volatile("cp.async.wait_group 1;" ::: "memory")
#define CP_WAIT0()  asm volatile("cp.async.wait_group 0;" ::: "memory")

__device__ __forceinline__ uint32_t pack1(float x, float y) {
    half2 hh = __floats2half2_rn(x, y);
    return *reinterpret_cast<uint32_t*>(&hh);
}

// ---------------- fp32 -> fp16 convert (x + 4 weights, one launch) -----------
// grid (1024, 8): y=0..3 -> quarters of x (4M elems); y=4..7 -> wq,wk,wv,wo.
__global__ void cvt_all_kernel(const float* __restrict__ x,
                               const float* __restrict__ w0, const float* __restrict__ w1,
                               const float* __restrict__ w2, const float* __restrict__ w3,
                               half* __restrict__ xo,
                               half* __restrict__ o0, half* __restrict__ o1,
                               half* __restrict__ o2, half* __restrict__ o3) {
    const int y = blockIdx.y;
    const float* s;
    half* d;
    if (y < 4) { s = x + (size_t)y * 1048576;  d = xo + (size_t)y * 1048576; }
    else if (y == 4) { s = w0; d = o0; }
    else if (y == 5) { s = w1; d = o1; }
    else if (y == 6) { s = w2; d = o2; }
    else             { s = w3; d = o3; }
    int i = (blockIdx.x * blockDim.x + threadIdx.x) * 4;   // 1024*256*4 = 1M
    float4 v = *(const float4*)(s + i);
    *(uint32_t*)(d + i)     = pack1(v.x, v.y);
    *(uint32_t*)(d + i + 2) = pack1(v.z, v.w);
}

// ---------------- RoPE tables ------------------------------------------------
__global__ void rope_table_kernel() {
    int idx = blockIdx.x * blockDim.x + threadIdx.x;   // 2048*32
    int p   = idx & 31;
    int pos = idx >> 5;
    double freq = pow(10000.0, -(double)(2 * p) / 64.0);
    double ang  = (double)pos * freq;
    g_cos[idx] = (float)cos(ang);
    g_sin[idx] = (float)sin(ang);
}

// ---------------- HMMA fp16 GEMM, cp.async 3-stage, BK=32, 512 thr -----------
// C[m][n] = sum_k A[m][k]*B[n][k], both operands fp16.
// CTA tile: 128(M) x 256(N) x 32(K).  16 warps as 2(M) x 8(N); warp tile 64x32.
// qkv=1: grid.z selects {0:Q(RoPE,x0.125) 1:K(RoPE) 2:V}; qkv=0: fp32 out.
#define G_RS     80                 // smem row stride bytes (32 fp16 + pad)
#define G_A      0
#define G_B      10240              // 128*80
#define G_STAGE  30720              // + 256*80
#define G_NSTAGE 3

__global__ __launch_bounds__(512, 1)
void gemm_mma(const half* __restrict__ A,
              const half* __restrict__ B0, const half* __restrict__ B1,
              const half* __restrict__ B2,
              float* __restrict__ Cf, half* __restrict__ Qd,
              half* __restrict__ Kd, half* __restrict__ Vd,
              const int* __restrict__ tp, int qkv)
{
    extern __shared__ char sm[];
    const uint32_t smb = (uint32_t)__cvta_generic_to_shared(sm);
    const int tid = threadIdx.x, lane = tid & 31, wid = tid >> 5;
    const int wm = wid & 1, wn = wid >> 1;           // 2(M) x 8(N) warps
    const int m0 = blockIdx.y * 128, n0 = blockIdx.x * 256;
    const int z  = blockIdx.z;
    const half* W = qkv ? ((z == 0) ? B0 : (z == 1) ? B1 : B2) : B0;
    const int mode = qkv ? ((z == 0) ? 2 : (z == 1) ? 3 : 1) : 0;

    // loader mappings (512 thr, 3 cpa16 each per stage)
    const int arow = tid >> 2, acol = (tid & 3) * 16;   // A: 4 thr/row, 16B each
    const int brow = tid >> 1, bcol = (tid & 1) * 32;   // B: 2 thr/row, 32B each
    const char* gA = (const char*)(A + (size_t)(m0 + arow) * D_MODEL) + acol;
    const char* gB = (const char*)(W + (size_t)(n0 + brow) * D_MODEL) + bcol;
    const uint32_t sA = smb + arow * G_RS + acol;
    const uint32_t sB = smb + G_B + brow * G_RS + bcol;

#define ISSUE(KT_, ST_) do { \
        const uint32_t so = (uint32_t)(ST_) * G_STAGE; \
        const int go = (KT_) * 64; \
        cpa16(so + sA,       gA + go); \
        cpa16(so + sB,       gB + go); \
        cpa16(so + sB + 16,  gB + go + 16); \
        CP_COMMIT(); \
    } while (0)

    float acc[4][4][4];
#pragma unroll
    for (int i = 0; i < 4; i++)
#pragma unroll
        for (int j = 0; j < 4; j++)
#pragma unroll
            for (int k = 0; k < 4; k++) acc[i][j][k] = 0.f;

    ISSUE(0, 0);
    ISSUE(1, 1);

    const int KT = D_MODEL / 32;   // 32
    for (int kt = 0; kt < KT; kt++) {
        if (kt + 1 < KT) CP_WAIT1(); else CP_WAIT0();
        __syncthreads();
        if (kt + 2 < KT) ISSUE(kt + 2, (kt + 2) % G_NSTAGE);

        const uint32_t stb = smb + (kt % G_NSTAGE) * G_STAGE;
#pragma unroll
        for (int kk = 0; kk < 2; kk++) {
            uint32_t ah[4][4], bh[2][4];
#pragma unroll
            for (int mi = 0; mi < 4; mi++) {
                uint32_t a = stb + (wm * 64 + mi * 16 + (lane & 15)) * G_RS
                           + kk * 32 + (lane >> 4) * 16;
                ldsm4(ah[mi], a);
            }
#pragma unroll
            for (int L = 0; L < 2; L++) {
                uint32_t a = stb + G_B
                           + (wn * 32 + L * 16 + (lane & 7) + ((lane >> 4) & 1) * 8) * G_RS
                           + kk * 32 + ((lane >> 3) & 1) * 16;
                ldsm4(bh[L], a);
            }
#pragma unroll
            for (int mi = 0; mi < 4; mi++)
#pragma unroll
                for (int nf = 0; nf < 4; nf++)
                    mma16816(acc[mi][nf], ah[mi], &bh[nf >> 1][(nf & 1) * 2]);
        }
    }

    // epilogue
#pragma unroll
    for (int mi = 0; mi < 4; mi++)
#pragma unroll
        for (int nf = 0; nf < 4; nf++) {
            const int row0 = m0 + wm * 64 + mi * 16 + (lane >> 2);
            const int col  = n0 + wn * 32 + nf * 8 + 2 * (lane & 3);
            float v0 = acc[mi][nf][0], v1 = acc[mi][nf][1];
            float v2 = acc[mi][nf][2], v3 = acc[mi][nf][3];
            if (mode >= 2) {  // RoPE
                const int p = (col & 63) >> 1;
                const int pos0 = tp[row0 & (SEQ - 1)];
                const int pos1 = tp[(row0 + 8) & (SEQ - 1)];
                const float c0 = g_cos[pos0 * 32 + p], s0 = g_sin[pos0 * 32 + p];
                const float c1 = g_cos[pos1 * 32 + p], s1 = g_sin[pos1 * 32 + p];
                float e0 = v0 * c0 - v1 * s0, o0 = v1 * c0 + v0 * s0;
                float e1 = v2 * c1 - v3 * s1, o1 = v3 * c1 + v2 * s1;
                v0 = e0; v1 = o0; v2 = e1; v3 = o1;
                if (mode == 2) { v0 *= 0.125f; v1 *= 0.125f; v2 *= 0.125f; v3 *= 0.125f; }
            }
            if (mode == 0) {
                *(float2*)(Cf + (size_t)row0 * D_MODEL + col)       = make_float2(v0, v1);
                *(float2*)(Cf + (size_t)(row0 + 8) * D_MODEL + col) = make_float2(v2, v3);
            } else {
                const int hh = col >> 6, d = col & 63;
                const int bb = row0 >> 11, ss = row0 & (SEQ - 1);
                size_t i0 = ((size_t)(bb * N_HEADS + hh) * SEQ + ss) * D_KV + d;
                size_t i1 = i0 + 8 * D_KV;
                half* dst = (mode == 2) ? Qd : (mode == 3) ? Kd : Vd;
                *(uint32_t*)(dst + i0) = pack1(v0, v1);
                *(uint32_t*)(dst + i1) = pack1(v2, v3);
            }
        }
#undef ISSUE
}

// ---------------- tensor-core flash attention (causal, shifted-exp softmax) --
// block 256 thr = 8 warps, each warp 16 q-rows; key tiles of 64.  Pure fp16 ops.
// __launch_bounds__(256, 2): cap 128 regs -> 2 CTAs/SM -> 4 warps/SMSP.
#define A_RS    144                 // 64 fp16 + pad
#define A_KT    (64*A_RS)           // 9216
#define A_STAGE (2*A_KT)            // 18432 (Kh, Vh)
#define ST_OFF  18432               // KV stages start (after 128-row Q tile)

__global__ __launch_bounds__(256, 2)
void attn_mma(const half* __restrict__ Qh_, const half* __restrict__ Kh_,
              const half* __restrict__ Vh_, half* __restrict__ Oh_)
{
    extern __shared__ char sm[];
    const uint32_t smb = (uint32_t)__cvta_generic_to_shared(sm);
    const int tid = threadIdx.x, lane = tid & 31, wid = tid >> 5;
    const int qt = gridDim.x - 1 - blockIdx.x;      // heavy blocks first
    const int q0 = qt * 128;
    const int h = blockIdx.y, b = blockIdx.z;
    const size_t hb = (size_t)(b * N_HEADS + h) * SEQ * D_KV;
    const int nt = 2 * qt + 2;

    const half* Qh = Qh_ + hb;
    const half* Kh = Kh_ + hb;
    const half* Vh = Vh_ + hb;

    // load Q tile
    {
        const int r = tid >> 1;
        const char* gqh = (const char*)(Qh + (size_t)(q0 + r) * D_KV);
        char* sq = sm + r * A_RS;
#pragma unroll
        for (int i = 0; i < 4; i++) {
            const int c = (tid & 1) * 64 + i * 16;
            *(uint4*)(sq + c) = *(const uint4*)(gqh + c);
        }
    }

    // KV loader mapping: 4 threads per row, 32B each (row = 128B)
    const int kr = tid >> 2;
    const int kc = (tid & 3) * 32;
    uint4 kbuf[2][2];
#define KV_LOAD(KT_) do { \
        const size_t roff = (size_t)((KT_) * 64 + kr) * D_KV; \
        const char* t0 = (const char*)(Kh + roff); \
        const char* t1 = (const char*)(Vh + roff); \
        kbuf[0][0] = *(const uint4*)(t0 + kc); kbuf[0][1] = *(const uint4*)(t0 + kc + 16); \
        kbuf[1][0] = *(const uint4*)(t1 + kc); kbuf[1][1] = *(const uint4*)(t1 + kc + 16); \
    } while (0)
#define KV_STORE(ST_) do { \
        char* dst = sm + ST_OFF + (ST_) * A_STAGE + kr * A_RS + kc; \
        *(uint4*)(dst)             = kbuf[0][0]; \
        *(uint4*)(dst + 16)        = kbuf[0][1]; \
        *(uint4*)(dst + A_KT)      = kbuf[1][0]; \
        *(uint4*)(dst + A_KT + 16) = kbuf[1][1]; \
    } while (0)

    KV_LOAD(0);
    KV_STORE(0);
    __syncthreads();

    // Q fragments
    uint32_t qh[4][4];
#pragma unroll
    for (int kk = 0; kk < 4; kk++) {
        uint32_t a = smb + (wid * 16 + (lane & 15)) * A_RS + kk * 32 + (lane >> 4) * 16;
        ldsm4(qh[kk], a);
    }

    float oacc[8][4];
#pragma unroll
    for (int i = 0; i < 8; i++)
#pragma unroll
        for (int j = 0; j < 4; j++) oacc[i][j] = 0.f;
    float ls0 = 0.f, ls1 = 0.f;
    const int wr0 = q0 + wid * 16;

    for (int kt = 0; kt < nt; kt++) {
        if (kt + 1 < nt) KV_LOAD(kt + 1);
        const uint32_t stb = smb + ST_OFF + (kt & 1) * A_STAGE;
        const int kbase = kt * 64;

        if (kbase <= wr0 + 15) {
            float sacc[8][4];
#pragma unroll
            for (int i = 0; i < 8; i++)
#pragma unroll
                for (int j = 0; j < 4; j++) sacc[i][j] = 0.f;

            // S = Q K^T
#pragma unroll
            for (int kk = 0; kk < 4; kk++) {
                uint32_t kbh[4][4];
#pragma unroll
                for (int L = 0; L < 4; L++) {
                    uint32_t a = stb + (L * 16 + (lane & 7) + ((lane >> 4) & 1) * 8) * A_RS
                               + kk * 32 + ((lane >> 3) & 1) * 16;
                    ldsm4(kbh[L], a);
                }
#pragma unroll
                for (int nf = 0; nf < 8; nf++)
                    mma16816(sacc[nf], qh[kk], &kbh[nf >> 1][(nf & 1) * 2]);
            }

            // mask + shifted exp (p = e^(s-6); shift cancels in normalization)
            const bool needm = (kbase + 63 > wr0);
#pragma unroll
            for (int nf = 0; nf < 8; nf++)
#pragma unroll
                for (int j = 0; j < 4; j++) {
                    float p = __expf(sacc[nf][j] - 6.0f);
                    if (needm) {
                        const int key = kbase + nf * 8 + 2 * (lane & 3) + (j & 1);
                        const int row = wr0 + (lane >> 2) + (j >> 1) * 8;
                        if (key > row) p = 0.f;
                    }
                    sacc[nf][j] = p;
                    if (j < 2) ls0 += p; else ls1 += p;
                }

            // O += P V
#pragma unroll
            for (int kk2 = 0; kk2 < 4; kk2++) {
                uint32_t vh[4][4];
#pragma unroll
                for (int dL = 0; dL < 4; dL++) {
                    uint32_t a = stb + A_KT
                               + (kk2 * 16 + (lane & 7) + ((lane >> 3) & 1) * 8) * A_RS
                               + dL * 32 + ((lane >> 4) & 1) * 16;
                    ldsm4t(vh[dL], a);
                }
                uint32_t ph[4];
                ph[0] = pack1(sacc[2*kk2][0],   sacc[2*kk2][1]);
                ph[1] = pack1(sacc[2*kk2][2],   sacc[2*kk2][3]);
                ph[2] = pack1(sacc[2*kk2+1][0], sacc[2*kk2+1][1]);
                ph[3] = pack1(sacc[2*kk2+1][2], sacc[2*kk2+1][3]);
#pragma unroll
                for (int df = 0; df < 8; df++)
                    mma16816(oacc[df], ph, &vh[df >> 1][(df & 1) * 2]);
            }
        }

        if (kt + 1 < nt) KV_STORE((kt + 1) & 1);
        __syncthreads();
    }

    // reduce row sums across quad
    ls0 += __shfl_xor_sync(0xffffffffu, ls0, 1);
    ls0 += __shfl_xor_sync(0xffffffffu, ls0, 2);
    ls1 += __shfl_xor_sync(0xffffffffu, ls1, 1);
    ls1 += __shfl_xor_sync(0xffffffffu, ls1, 2);
    const float inv0 = 1.f / ls0, inv1 = 1.f / ls1;

    const int row0 = q0 + wid * 16 + (lane >> 2);
#pragma unroll
    for (int df = 0; df < 8; df++) {
        const int d = df * 8 + 2 * (lane & 3);
        const float v0 = oacc[df][0] * inv0, v1 = oacc[df][1] * inv0;
        const float v2 = oacc[df][2] * inv1, v3 = oacc[df][3] * inv1;
        const size_t i0 = (size_t)(b * SEQ + row0) * D_MODEL + h * D_KV + d;
        const size_t i1 = i0 + (size_t)8 * D_MODEL;
        *(uint32_t*)(Oh_ + i0) = pack1(v0, v1);
        *(uint32_t*)(Oh_ + i1) = pack1(v2, v3);
    }
}

// ---------------- host launcher ----------------------------------------------
extern "C" void kernel_launch(void* const* d_in, const int* in_sizes, int n_in,
                              void* d_out, int out_size)
{
    const float* x  = (const float*)d_in[0];
    const float* wq = (const float*)d_in[1];
    const float* wk = (const float*)d_in[2];
    const float* wv = (const float*)d_in[3];
    const float* wo = (const float*)d_in[4];
    const int*   tp = (const int*)d_in[5];
    float* out = (float*)d_out;

    half *xh, *wqh, *wkh, *wvh, *woh, *Qh, *Kh, *Vh, *Oh;
    cudaGetSymbolAddress((void**)&xh, g_xh);
    cudaGetSymbolAddress((void**)&wqh, g_wqh); cudaGetSymbolAddress((void**)&wkh, g_wkh);
    cudaGetSymbolAddress((void**)&wvh, g_wvh); cudaGetSymbolAddress((void**)&woh, g_woh);
    cudaGetSymbolAddress((void**)&Qh, g_Qh);   cudaGetSymbolAddress((void**)&Kh, g_Kh);
    cudaGetSymbolAddress((void**)&Vh, g_Vh);   cudaGetSymbolAddress((void**)&Oh, g_Oh);

    const int gemm_smem = G_NSTAGE * G_STAGE;                 // 92160
    const int attn_smem = ST_OFF + 2 * A_STAGE;               // 55296
    cudaFuncSetAttribute(gemm_mma, cudaFuncAttributeMaxDynamicSharedMemorySize, gemm_smem);
    cudaFuncSetAttribute(attn_mma, cudaFuncAttributeMaxDynamicSharedMemorySize, attn_smem);

    // converts / tables (2 launches)
    cvt_all_kernel<<<dim3(1024, 8), 256>>>(x, wq, wk, wv, wo,
                                           xh, wqh, wkh, wvh, woh);
    rope_table_kernel<<<SEQ * 32 / 256, 256>>>();

    // fused QKV projections (one launch, 512 threads)
    dim3 qkvgrid(D_MODEL / 256, M_TOTAL / 128, 3);   // (4, 32, 3)
    gemm_mma<<<qkvgrid, 512, gemm_smem>>>(xh, wqh, wkh, wvh,
                                          nullptr, Qh, Kh, Vh, tp, 1);

    // attention
    dim3 agrid(SEQ / 128, N_HEADS, BATCH);           // (16,16,2)
    attn_mma<<<agrid, 256, attn_smem>>>(Qh, Kh, Vh, Oh);

    // output projection
    dim3 ogrid(D_MODEL / 256, M_TOTAL / 128, 1);
    gemm_mma<<<ogrid, 512, gemm_smem>>>(Oh, woh, nullptr, nullptr,
                                        out, nullptr, nullptr, nullptr, tp, 0);
}

// round 15
// speedup vs baseline: 1.4722x; 1.0214x over previous
#include <cuda_runtime.h>
#include <cuda_fp16.h>
#include <math.h>
#include <cstdint>

#define D_MODEL 1024
#define N_HEADS 16
#define D_KV    64
#define BATCH   2
#define SEQ     2048
#define M_TOTAL (BATCH*SEQ)     // 4096

// ---------------- scratch (device globals) ----------------------------------
__device__ half g_xh[(size_t)M_TOTAL*D_MODEL];
__device__ half g_wqh[(size_t)D_MODEL*D_MODEL];
__device__ half g_wkh[(size_t)D_MODEL*D_MODEL];
__device__ half g_wvh[(size_t)D_MODEL*D_MODEL];
__device__ half g_woh[(size_t)D_MODEL*D_MODEL];
__device__ half g_Qh[(size_t)M_TOTAL*D_MODEL];   // [b,h,s,d]
__device__ half g_Kh[(size_t)M_TOTAL*D_MODEL];   // [b,h,s,d]
__device__ half g_Vh[(size_t)M_TOTAL*D_MODEL];
__device__ half g_Oh[(size_t)M_TOTAL*D_MODEL];   // [b*s, h*64+d]
__device__ float g_cos[SEQ*(D_KV/2)];
__device__ float g_sin[SEQ*(D_KV/2)];

// ---------------- mma / ldmatrix / cp.async helpers --------------------------
__device__ __forceinline__ void ldsm4(uint32_t* r, uint32_t a) {
    asm volatile("ldmatrix.sync.aligned.m8n8.x4.shared.b16 {%0,%1,%2,%3}, [%4];"
        : "=r"(r[0]), "=r"(r[1]), "=r"(r[2]), "=r"(r[3]) : "r"(a));
}
__device__ __forceinline__ void ldsm4t(uint32_t* r, uint32_t a) {
    asm volatile("ldmatrix.sync.aligned.m8n8.x4.trans.shared.b16 {%0,%1,%2,%3}, [%4];"
        : "=r"(r[0]), "=r"(r[1]), "=r"(r[2]), "=r"(r[3]) : "r"(a));
}
__device__ __forceinline__ void mma16816(float* c, const uint32_t* a, const uint32_t* b) {
    asm volatile("mma.sync.aligned.m16n8k16.row.col.f32.f16.f16.f32 "
        "{%0,%1,%2,%3}, {%4,%5,%6,%7}, {%8,%9}, {%0,%1,%2,%3};"
        : "+f"(c[0]), "+f"(c[1]), "+f"(c[2]), "+f"(c[3])
        : "r"(a[0]), "r"(a[1]), "r"(a[2]), "r"(a[3]), "r"(b[0]), "r"(b[1]));
}
__device__ __forceinline__ void cpa16(uint32_t s, const void* g) {
    asm volatile("cp.async.cg.shared.global [%0], [%1], 16;" :: "r"(s), "l"(g));
}
#define CP_COMMIT() asm volatile("cp.async.commit_group;" ::: "memory")
#define CP_WAIT1()  asm volatile("cp.async.wait_group 1;" ::: "memory")
#define CP_WAIT0()  asm volatile("cp.async.wait_group 0;" ::: "memory")

__device__ __forceinline__ uint32_t pack1(float x, float y) {
    half2 hh = __floats2half2_rn(x, y);
    return *reinterpret_cast<uint32_t*>(&hh);
}

// ---------------- fp32 -> fp16 convert (x + 4 weights, one launch) -----------
// grid (512, 8): y=0..3 -> quarters of x; y=4..7 -> wq,wk,wv,wo. 8 elems/thread.
__global__ void cvt_all_kernel(const float* __restrict__ x,
                               const float* __restrict__ w0, const float* __restrict__ w1,
                               const float* __restrict__ w2, const float* __restrict__ w3,
                               half* __restrict__ xo,
                               half* __restrict__ o0, half* __restrict__ o1,
                               half* __restrict__ o2, half* __restrict__ o3) {
    const int y = blockIdx.y;
    const float* s;
    half* d;
    if (y < 4) { s = x + (size_t)y * 1048576;  d = xo + (size_t)y * 1048576; }
    else if (y == 4) { s = w0; d = o0; }
    else if (y == 5) { s = w1; d = o1; }
    else if (y == 6) { s = w2; d = o2; }
    else             { s = w3; d = o3; }
    int i = (blockIdx.x * blockDim.x + threadIdx.x) * 8;
    float4 v0 = *(const float4*)(s + i);
    float4 v1 = *(const float4*)(s + i + 4);
    *(uint32_t*)(d + i)     = pack1(v0.x, v0.y);
    *(uint32_t*)(d + i + 2) = pack1(v0.z, v0.w);
    *(uint32_t*)(d + i + 4) = pack1(v1.x, v1.y);
    *(uint32_t*)(d + i + 6) = pack1(v1.z, v1.w);
}

// ---------------- RoPE tables ------------------------------------------------
__global__ void rope_table_kernel() {
    int idx = blockIdx.x * blockDim.x + threadIdx.x;   // 2048*32
    int p   = idx & 31;
    int pos = idx >> 5;
    double freq = pow(10000.0, -(double)(2 * p) / 64.0);
    double ang  = (double)pos * freq;
    g_cos[idx] = (float)cos(ang);
    g_sin[idx] = (float)sin(ang);
}

// ---------------- HMMA fp16 GEMM, cp.async 3-stage, 256 thr, 2 CTA/SM --------
// C[m][n] = sum_k A[m][k]*B[n][k], both operands fp16.
// CTA tile: 128(M) x 128(N) x 32(K).  8 warps as 2(M) x 4(N); warp tile 64x32.
// 2 CTAs/SM = 2 independent barrier domains -> ldsm/MMA phases overlap across CTAs.
// qkv=1: grid.z selects {0:Q(RoPE,x0.125) 1:K(RoPE) 2:V}; qkv=0: fp32 out.
#define G_RS     80                 // smem row stride bytes (32 fp16 + pad)
#define G_B      10240              // 128*80
#define G_STAGE  20480              // A tile + B tile
#define G_NSTAGE 3

__global__ __launch_bounds__(256, 2)
void gemm_mma(const half* __restrict__ A,
              const half* __restrict__ B0, const half* __restrict__ B1,
              const half* __restrict__ B2,
              float* __restrict__ Cf, half* __restrict__ Qd,
              half* __restrict__ Kd, half* __restrict__ Vd,
              const int* __restrict__ tp, int qkv)
{
    extern __shared__ char sm[];
    const uint32_t smb = (uint32_t)__cvta_generic_to_shared(sm);
    const int tid = threadIdx.x, lane = tid & 31, wid = tid >> 5;
    const int wm = wid & 1, wn = wid >> 1;           // 2(M) x 4(N) warps
    const int m0 = blockIdx.y * 128, n0 = blockIdx.x * 128;
    const int z  = blockIdx.z;
    const half* W = qkv ? ((z == 0) ? B0 : (z == 1) ? B1 : B2) : B0;
    const int mode = qkv ? ((z == 0) ? 2 : (z == 1) ? 3 : 1) : 0;

    // loader mappings (256 thr, 4 cpa16 each per stage: 2 A + 2 B)
    const int lrow = tid >> 1, lcol = (tid & 1) * 32;   // 2 thr/row, 32B each
    const char* gA = (const char*)(A + (size_t)(m0 + lrow) * D_MODEL) + lcol;
    const char* gB = (const char*)(W + (size_t)(n0 + lrow) * D_MODEL) + lcol;
    const uint32_t sA = smb + lrow * G_RS + lcol;
    const uint32_t sB = smb + G_B + lrow * G_RS + lcol;

#define ISSUE(KT_, ST_) do { \
        const uint32_t so = (uint32_t)(ST_) * G_STAGE; \
        const int go = (KT_) * 64; \
        cpa16(so + sA,       gA + go); \
        cpa16(so + sA + 16,  gA + go + 16); \
        cpa16(so + sB,       gB + go); \
        cpa16(so + sB + 16,  gB + go + 16); \
        CP_COMMIT(); \
    } while (0)

    float acc[4][4][4];
#pragma unroll
    for (int i = 0; i < 4; i++)
#pragma unroll
        for (int j = 0; j < 4; j++)
#pragma unroll
            for (int k = 0; k < 4; k++) acc[i][j][k] = 0.f;

    ISSUE(0, 0);
    ISSUE(1, 1);

    const int KT = D_MODEL / 32;   // 32
    for (int kt = 0; kt < KT; kt++) {
        if (kt + 1 < KT) CP_WAIT1(); else CP_WAIT0();
        __syncthreads();
        if (kt + 2 < KT) ISSUE(kt + 2, (kt + 2) % G_NSTAGE);

        const uint32_t stb = smb + (kt % G_NSTAGE) * G_STAGE;
#pragma unroll
        for (int kk = 0; kk < 2; kk++) {
            uint32_t ah[4][4], bh[2][4];
#pragma unroll
            for (int mi = 0; mi < 4; mi++) {
                uint32_t a = stb + (wm * 64 + mi * 16 + (lane & 15)) * G_RS
                           + kk * 32 + (lane >> 4) * 16;
                ldsm4(ah[mi], a);
            }
#pragma unroll
            for (int L = 0; L < 2; L++) {
                uint32_t a = stb + G_B
                           + (wn * 32 + L * 16 + (lane & 7) + ((lane >> 4) & 1) * 8) * G_RS
                           + kk * 32 + ((lane >> 3) & 1) * 16;
                ldsm4(bh[L], a);
            }
#pragma unroll
            for (int mi = 0; mi < 4; mi++)
#pragma unroll
                for (int nf = 0; nf < 4; nf++)
                    mma16816(acc[mi][nf], ah[mi], &bh[nf >> 1][(nf & 1) * 2]);
        }
    }

    // epilogue
#pragma unroll
    for (int mi = 0; mi < 4; mi++)
#pragma unroll
        for (int nf = 0; nf < 4; nf++) {
            const int row0 = m0 + wm * 64 + mi * 16 + (lane >> 2);
            const int col  = n0 + wn * 32 + nf * 8 + 2 * (lane & 3);
            float v0 = acc[mi][nf][0], v1 = acc[mi][nf][1];
            float v2 = acc[mi][nf][2], v3 = acc[mi][nf][3];
            if (mode >= 2) {  // RoPE
                const int p = (col & 63) >> 1;
                const int pos0 = tp[row0 & (SEQ - 1)];
                const int pos1 = tp[(row0 + 8) & (SEQ - 1)];
                const float c0 = g_cos[pos0 * 32 + p], s0 = g_sin[pos0 * 32 + p];
                const float c1 = g_cos[pos1 * 32 + p], s1 = g_sin[pos1 * 32 + p];
                float e0 = v0 * c0 - v1 * s0, o0 = v1 * c0 + v0 * s0;
                float e1 = v2 * c1 - v3 * s1, o1 = v3 * c1 + v2 * s1;
                v0 = e0; v1 = o0; v2 = e1; v3 = o1;
                if (mode == 2) { v0 *= 0.125f; v1 *= 0.125f; v2 *= 0.125f; v3 *= 0.125f; }
            }
            if (mode == 0) {
                *(float2*)(Cf + (size_t)row0 * D_MODEL + col)       = make_float2(v0, v1);
                *(float2*)(Cf + (size_t)(row0 + 8) * D_MODEL + col) = make_float2(v2, v3);
            } else {
                const int hh = col >> 6, d = col & 63;
                const int bb = row0 >> 11, ss = row0 & (SEQ - 1);
                size_t i0 = ((size_t)(bb * N_HEADS + hh) * SEQ + ss) * D_KV + d;
                size_t i1 = i0 + 8 * D_KV;
                half* dst = (mode == 2) ? Qd : (mode == 3) ? Kd : Vd;
                *(uint32_t*)(dst + i0) = pack1(v0, v1);
                *(uint32_t*)(dst + i1) = pack1(v2, v3);
            }
        }
#undef ISSUE
}

// ---------------- tensor-core flash attention (causal, shifted-exp softmax) --
// block 256 thr = 8 warps, each warp 16 q-rows; key tiles of 64.  Pure fp16 ops.
// __launch_bounds__(256, 2): cap 128 regs -> 2 CTAs/SM -> 4 warps/SMSP.
#define A_RS    144                 // 64 fp16 + pad
#define A_KT    (64*A_RS)           // 9216
#define A_STAGE (2*A_KT)            // 18432 (Kh, Vh)
#define ST_OFF  18432               // KV stages start (after 128-row Q tile)

__global__ __launch_bounds__(256, 2)
void attn_mma(const half* __restrict__ Qh_, const half* __restrict__ Kh_,
              const half* __restrict__ Vh_, half* __restrict__ Oh_)
{
    extern __shared__ char sm[];
    const uint32_t smb = (uint32_t)__cvta_generic_to_shared(sm);
    const int tid = threadIdx.x, lane = tid & 31, wid = tid >> 5;
    const int qt = gridDim.x - 1 - blockIdx.x;      // heavy blocks first
    const int q0 = qt * 128;
    const int h = blockIdx.y, b = blockIdx.z;
    const size_t hb = (size_t)(b * N_HEADS + h) * SEQ * D_KV;
    const int nt = 2 * qt + 2;

    const half* Qh = Qh_ + hb;
    const half* Kh = Kh_ + hb;
    const half* Vh = Vh_ + hb;

    // load Q tile
    {
        const int r = tid >> 1;
        const char* gqh = (const char*)(Qh + (size_t)(q0 + r) * D_KV);
        char* sq = sm + r * A_RS;
#pragma unroll
        for (int i = 0; i < 4; i++) {
            const int c = (tid & 1) * 64 + i * 16;
            *(uint4*)(sq + c) = *(const uint4*)(gqh + c);
        }
    }

    // KV loader mapping: 4 threads per row, 32B each (row = 128B)
    const int kr = tid >> 2;
    const int kc = (tid & 3) * 32;
    uint4 kbuf[2][2];
#define KV_LOAD(KT_) do { \
        const size_t roff = (size_t)((KT_) * 64 + kr) * D_KV; \
        const char* t0 = (const char*)(Kh + roff); \
        const char* t1 = (const char*)(Vh + roff); \
        kbuf[0][0] = *(const uint4*)(t0 + kc); kbuf[0][1] = *(const uint4*)(t0 + kc + 16); \
        kbuf[1][0] = *(const uint4*)(t1 + kc); kbuf[1][1] = *(const uint4*)(t1 + kc + 16); \
    } while (0)
#define KV_STORE(ST_) do { \
        char* dst = sm + ST_OFF + (ST_) * A_STAGE + kr * A_RS + kc; \
        *(uint4*)(dst)             = kbuf[0][0]; \
        *(uint4*)(dst + 16)        = kbuf[0][1]; \
        *(uint4*)(dst + A_KT)      = kbuf[1][0]; \
        *(uint4*)(dst + A_KT + 16) = kbuf[1][1]; \
    } while (0)

    KV_LOAD(0);
    KV_STORE(0);
    __syncthreads();

    // Q fragments
    uint32_t qh[4][4];
#pragma unroll
    for (int kk = 0; kk < 4; kk++) {
        uint32_t a = smb + (wid * 16 + (lane & 15)) * A_RS + kk * 32 + (lane >> 4) * 16;
        ldsm4(qh[kk], a);
    }

    float oacc[8][4];
#pragma unroll
    for (int i = 0; i < 8; i++)
#pragma unroll
        for (int j = 0; j < 4; j++) oacc[i][j] = 0.f;
    float ls0 = 0.f, ls1 = 0.f;
    const int wr0 = q0 + wid * 16;

    for (int kt = 0; kt < nt; kt++) {
        if (kt + 1 < nt) KV_LOAD(kt + 1);
        const uint32_t stb = smb + ST_OFF + (kt & 1) * A_STAGE;
        const int kbase = kt * 64;

        if (kbase <= wr0 + 15) {
            float sacc[8][4];
#pragma unroll
            for (int i = 0; i < 8; i++)
#pragma unroll
                for (int j = 0; j < 4; j++) sacc[i][j] = 0.f;

            // S = Q K^T
#pragma unroll
            for (int kk = 0; kk < 4; kk++) {
                uint32_t kbh[4][4];
#pragma unroll
                for (int L = 0; L < 4; L++) {
                    uint32_t a = stb + (L * 16 + (lane & 7) + ((lane >> 4) & 1) * 8) * A_RS
                               + kk * 32 + ((lane >> 3) & 1) * 16;
                    ldsm4(kbh[L], a);
                }
#pragma unroll
                for (int nf = 0; nf < 8; nf++)
                    mma16816(sacc[nf], qh[kk], &kbh[nf >> 1][(nf & 1) * 2]);
            }

            // mask + shifted exp (p = e^(s-6); shift cancels in normalization)
            const bool needm = (kbase + 63 > wr0);
#pragma unroll
            for (int nf = 0; nf < 8; nf++)
#pragma unroll
                for (int j = 0; j < 4; j++) {
                    float p = __expf(sacc[nf][j] - 6.0f);
                    if (needm) {
                        const int key = kbase + nf * 8 + 2 * (lane & 3) + (j & 1);
                        const int row = wr0 + (lane >> 2) + (j >> 1) * 8;
                        if (key > row) p = 0.f;
                    }
                    sacc[nf][j] = p;
                    if (j < 2) ls0 += p; else ls1 += p;
                }

            // O += P V
#pragma unroll
            for (int kk2 = 0; kk2 < 4; kk2++) {
                uint32_t vh[4][4];
#pragma unroll
                for (int dL = 0; dL < 4; dL++) {
                    uint32_t a = stb + A_KT
                               + (kk2 * 16 + (lane & 7) + ((lane >> 3) & 1) * 8) * A_RS
                               + dL * 32 + ((lane >> 4) & 1) * 16;
                    ldsm4t(vh[dL], a);
                }
                uint32_t ph[4];
                ph[0] = pack1(sacc[2*kk2][0],   sacc[2*kk2][1]);
                ph[1] = pack1(sacc[2*kk2][2],   sacc[2*kk2][3]);
                ph[2] = pack1(sacc[2*kk2+1][0], sacc[2*kk2+1][1]);
                ph[3] = pack1(sacc[2*kk2+1][2], sacc[2*kk2+1][3]);
#pragma unroll
                for (int df = 0; df < 8; df++)
                    mma16816(oacc[df], ph, &vh[df >> 1][(df & 1) * 2]);
            }
        }

        if (kt + 1 < nt) KV_STORE((kt + 1) & 1);
        __syncthreads();
    }

    // reduce row sums across quad
    ls0 += __shfl_xor_sync(0xffffffffu, ls0, 1);
    ls0 += __shfl_xor_sync(0xffffffffu, ls0, 2);
    ls1 += __shfl_xor_sync(0xffffffffu, ls1, 1);
    ls1 += __shfl_xor_sync(0xffffffffu, ls1, 2);
    const float inv0 = 1.f / ls0, inv1 = 1.f / ls1;

    const int row0 = q0 + wid * 16 + (lane >> 2);
#pragma unroll
    for (int df = 0; df < 8; df++) {
        const int d = df * 8 + 2 * (lane & 3);
        const float v0 = oacc[df][0] * inv0, v1 = oacc[df][1] * inv0;
        const float v2 = oacc[df][2] * inv1, v3 = oacc[df][3] * inv1;
        const size_t i0 = (size_t)(b * SEQ + row0) * D_MODEL + h * D_KV + d;
        const size_t i1 = i0 + (size_t)8 * D_MODEL;
        *(uint32_t*)(Oh_ + i0) = pack1(v0, v1);
        *(uint32_t*)(Oh_ + i1) = pack1(v2, v3);
    }
}

// ---------------- host launcher ----------------------------------------------
extern "C" void kernel_launch(void* const* d_in, const int* in_sizes, int n_in,
                              void* d_out, int out_size)
{
    const float* x  = (const float*)d_in[0];
    const float* wq = (const float*)d_in[1];
    const float* wk = (const float*)d_in[2];
    const float* wv = (const float*)d_in[3];
    const float* wo = (const float*)d_in[4];
    const int*   tp = (const int*)d_in[5];
    float* out = (float*)d_out;

    half *xh, *wqh, *wkh, *wvh, *woh, *Qh, *Kh, *Vh, *Oh;
    cudaGetSymbolAddress((void**)&xh, g_xh);
    cudaGetSymbolAddress((void**)&wqh, g_wqh); cudaGetSymbolAddress((void**)&wkh, g_wkh);
    cudaGetSymbolAddress((void**)&wvh, g_wvh); cudaGetSymbolAddress((void**)&woh, g_woh);
    cudaGetSymbolAddress((void**)&Qh, g_Qh);   cudaGetSymbolAddress((void**)&Kh, g_Kh);
    cudaGetSymbolAddress((void**)&Vh, g_Vh);   cudaGetSymbolAddress((void**)&Oh, g_Oh);

    const int gemm_smem = G_NSTAGE * G_STAGE;                 // 61440
    const int attn_smem = ST_OFF + 2 * A_STAGE;               // 55296
    cudaFuncSetAttribute(gemm_mma, cudaFuncAttributeMaxDynamicSharedMemorySize, gemm_smem);
    cudaFuncSetAttribute(attn_mma, cudaFuncAttributeMaxDynamicSharedMemorySize, attn_smem);

    // converts / tables (2 launches)
    cvt_all_kernel<<<dim3(512, 8), 256>>>(x, wq, wk, wv, wo,
                                          xh, wqh, wkh, wvh, woh);
    rope_table_kernel<<<SEQ * 32 / 256, 256>>>();

    // fused QKV projections (one launch, 256 threads, 2 CTAs/SM)
    dim3 qkvgrid(D_MODEL / 128, M_TOTAL / 128, 3);   // (8, 32, 3)
    gemm_mma<<<qkvgrid, 256, gemm_smem>>>(xh, wqh, wkh, wvh,
                                          nullptr, Qh, Kh, Vh, tp, 1);

    // attention
    dim3 agrid(SEQ / 128, N_HEADS, BATCH);           // (16,16,2)
    attn_mma<<<agrid, 256, attn_smem>>>(Qh, Kh, Vh, Oh);

    // output projection
    dim3 ogrid(D_MODEL / 128, M_TOTAL / 128, 1);
    gemm_mma<<<ogrid, 256, gemm_smem>>>(Oh, woh, nullptr, nullptr,
                                        out, nullptr, nullptr, nullptr, tp, 0);
}